// round 8
// baseline (speedup 1.0000x reference)
#include <cuda_runtime.h>
#include <cuda_bf16.h>
#include <cstdint>
#include <cstddef>

// Problem dims (fixed)
#define T_STEPS 100
#define BATCH   256
#define IN_DIM  784
#define HID     1024
#define OUT_DIM 10
#define MROWS   25600
#define BH      262144
#define BO      2560
#define HID_OUT ((size_t)MROWS * HID)
#define THRESH 0.9f
#define DECAY  0.6f

// GEMM1: int8 3-plane cascade. CTA tile 128m x 64n, BK=32, K padded to 800
// -> 25 slabs, 6-stage cp.async ring (preload 5, wait_group 4).
#define KPAD 800
#define NSLAB 25
#define NSTAGE 6
#define A_STAGE_B 6144u                 // 128 rows * 48B (32B data + pad)
#define B_PLANE_B 3072u                 // 64 rows * 48B
#define STAGE_B   (A_STAGE_B + 3u * B_PLANE_B)   // 15360
#define SMEM_TOTAL (NSTAGE * STAGE_B)   // 92160 -> 2 CTAs/SM
#define WELEM ((size_t)HID * KPAD)      // 819200 int8 per plane

// quantization scales (powers of 2 -> exact splits)
#define S1 9.765625e-4f        // 2^-10
#define S2 7.62939453125e-6f   // 2^-17
#define S3 5.9604644775390625e-8f  // 2^-24

// ------------------------- scratch (device globals) -----------------------
__device__ int8_t g_Xq[(size_t)MROWS * KPAD];     // 20.5 MB, 0/1, K-padded
__device__ int8_t g_W1q[3 * WELEM];               // 3 planes, [n][k], K-padded
__device__ float  g_U1[(size_t)MROWS * HID];      // 104.9 MB
__device__ float  g_U2[(size_t)MROWS * OUT_DIM];  // 1.0 MB

// ------------------------- helpers ---------------------------------------
__device__ __forceinline__ uint32_t smem_u32(const void* p) {
    uint32_t a;
    asm("{ .reg .u64 t; cvta.to.shared.u64 t, %1; cvt.u32.u64 %0, t; }" : "=r"(a) : "l"(p));
    return a;
}
__device__ __forceinline__ void cpa16(uint32_t s, const void* g) {
    asm volatile("cp.async.cg.shared.global [%0], [%1], 16;\n" :: "r"(s), "l"(g));
}
__device__ __forceinline__ void ldsm_x4(uint32_t& r0, uint32_t& r1, uint32_t& r2, uint32_t& r3, uint32_t addr) {
    asm volatile("ldmatrix.sync.aligned.m8n8.x4.shared.b16 {%0,%1,%2,%3}, [%4];\n"
                 : "=r"(r0), "=r"(r1), "=r"(r2), "=r"(r3) : "r"(addr));
}
__device__ __forceinline__ void ldsm_x2(uint32_t& r0, uint32_t& r1, uint32_t addr) {
    asm volatile("ldmatrix.sync.aligned.m8n8.x2.shared.b16 {%0,%1}, [%2];\n"
                 : "=r"(r0), "=r"(r1) : "r"(addr));
}
__device__ __forceinline__ void imma16832(int* d, const uint32_t* a, uint32_t b0, uint32_t b1) {
    asm volatile(
        "mma.sync.aligned.m16n8k32.row.col.s32.s8.s8.s32 "
        "{%0,%1,%2,%3}, {%4,%5,%6,%7}, {%8,%9}, {%0,%1,%2,%3};\n"
        : "+r"(d[0]), "+r"(d[1]), "+r"(d[2]), "+r"(d[3])
        : "r"(a[0]), "r"(a[1]), "r"(a[2]), "r"(a[3]), "r"(b0), "r"(b1));
}

// ------------------------- fused prep kernel -------------------------------
// Blocks [0, 5000): X fp32 -> int8 0/1, K-padded [25600][800]
// Blocks [5000, 8200): W1 -> 3-plane int8 cascade, transposed [n][k]
// Blocks [8200, 8450): zero U2
#define PREPX_BLKS 5000
#define PREPW_BLKS 3200
#define ZERO_BLKS  250
__global__ void prep_kernel(const float* __restrict__ x, const float* __restrict__ w1) {
    const int bid = blockIdx.x;
    if (bid < PREPX_BLKS) {
        int i = bid * 256 + threadIdx.x;          // < 1,280,000 (16-elem chunks)
        int row = i / 50, c = i % 50;
        uint8_t q[16];
        if (c < 49) {
            const float4* src = (const float4*)(x + (size_t)row * IN_DIM + c * 16);
#pragma unroll
            for (int j = 0; j < 4; j++) {
                float4 v = src[j];
                q[4 * j]     = (v.x != 0.f) ? 1 : 0;
                q[4 * j + 1] = (v.y != 0.f) ? 1 : 0;
                q[4 * j + 2] = (v.z != 0.f) ? 1 : 0;
                q[4 * j + 3] = (v.w != 0.f) ? 1 : 0;
            }
        } else {
#pragma unroll
            for (int j = 0; j < 16; j++) q[j] = 0;
        }
        *reinterpret_cast<uint4*>(g_Xq + (size_t)row * KPAD + c * 16) =
            *reinterpret_cast<uint4*>(q);
    } else if (bid < PREPX_BLKS + PREPW_BLKS) {
        int i = (bid - PREPX_BLKS) * 256 + threadIdx.x;   // < 819200
        int n = i / KPAD, k = i % KPAD;
        float w = (k < IN_DIM) ? w1[(size_t)k * HID + n] : 0.0f;
        float q1 = fminf(fmaxf(rintf(w * 1024.f), -127.f), 127.f);
        float r1 = w - q1 * S1;
        float q2 = fminf(fmaxf(rintf(r1 * 131072.f), -127.f), 127.f);
        float r2 = r1 - q2 * S2;
        float q3 = fminf(fmaxf(rintf(r2 * 16777216.f), -127.f), 127.f);
        size_t off = (size_t)n * KPAD + k;
        g_W1q[off]             = (int8_t)(int)q1;
        g_W1q[WELEM + off]     = (int8_t)(int)q2;
        g_W1q[2 * WELEM + off] = (int8_t)(int)q3;
    } else {
        int i = (bid - PREPX_BLKS - PREPW_BLKS) * 256 + threadIdx.x;  // < 64000
        reinterpret_cast<float4*>(g_U2)[i] = make_float4(0.f, 0.f, 0.f, 0.f);
    }
}

// ------------------------- GEMM1 (int8 3-plane) ---------------------------
// 8 warps 4m x 2n, warp tile 32x32; exact s32 accumulation per plane,
// fp32 combine in epilogue.
__global__ __launch_bounds__(256, 2) void gemm1_kernel() {
    extern __shared__ char smem[];
    const uint32_t sbase = smem_u32(smem);

    const int tid = threadIdx.x;
    const int bn0 = blockIdx.x * 64;
    const int bm0 = blockIdx.y * 128;

    const int lane   = tid & 31;
    const int wid    = tid >> 5;
    const int warp_m = wid >> 1;   // 0..3 (32 rows each)
    const int warp_n = wid & 1;    // 0..1 (32 cols each)

    int d[3][2][4][4];             // [plane][mt][nt][frag]
#pragma unroll
    for (int p = 0; p < 3; p++)
#pragma unroll
        for (int i = 0; i < 2; i++)
#pragma unroll
            for (int j = 0; j < 4; j++)
#pragma unroll
                for (int k = 0; k < 4; k++) d[p][i][j][k] = 0;

    // producers
    const int arow = tid >> 1, ahalf = tid & 1;
    const int8_t* agp = g_Xq + (size_t)(bm0 + arow) * KPAD + ahalf * 16;
    const uint32_t a_dst = sbase + arow * 48 + ahalf * 16;

    const int bpl1 = tid >> 7;                 // 0..1
    const int brow1 = (tid & 127) >> 1, bhalf1 = tid & 1;
    const int8_t* bgp1 = g_W1q + (size_t)bpl1 * WELEM + (size_t)(bn0 + brow1) * KPAD + bhalf1 * 16;
    const uint32_t b_dst1 = sbase + A_STAGE_B + bpl1 * B_PLANE_B + brow1 * 48 + bhalf1 * 16;

    const int brow2 = (tid & 127) >> 1, bhalf2 = tid & 1;   // plane 2, tid < 128
    const int8_t* bgp2 = g_W1q + 2 * WELEM + (size_t)(bn0 + brow2) * KPAD + bhalf2 * 16;
    const uint32_t b_dst2 = sbase + A_STAGE_B + 2 * B_PLANE_B + brow2 * 48 + bhalf2 * 16;
    const bool do_b2 = (tid < 128);

#define LOAD_STAGE(slot, kt) do {                                                   \
        uint32_t so = (slot) * STAGE_B;                                             \
        cpa16(a_dst + so,  agp + (size_t)(kt) * 32);                                \
        cpa16(b_dst1 + so, bgp1 + (size_t)(kt) * 32);                               \
        if (do_b2) cpa16(b_dst2 + so, bgp2 + (size_t)(kt) * 32);                    \
        asm volatile("cp.async.commit_group;\n" ::: "memory");                      \
    } while (0)

    LOAD_STAGE(0, 0);
    LOAD_STAGE(1, 1);
    LOAD_STAGE(2, 2);
    LOAD_STAGE(3, 3);
    LOAD_STAGE(4, 4);

    for (int kt = 0; kt < NSLAB; kt++) {
        const int cur = kt % NSTAGE;
        asm volatile("cp.async.wait_group 4;\n" ::: "memory");
        __syncthreads();

        if (kt + 5 < NSLAB) {
            LOAD_STAGE((kt + 5) % NSTAGE, kt + 5);
        } else {
            asm volatile("cp.async.commit_group;\n" ::: "memory");
        }

        const uint32_t so = sbase + cur * STAGE_B;

        // A fragments: 2 m16 tiles, shared by all 3 planes
        uint32_t a[2][4];
#pragma unroll
        for (int mt = 0; mt < 2; mt++) {
            uint32_t addr = so + (warp_m * 32 + mt * 16 + (lane & 15)) * 48 + (lane >> 4) * 16;
            ldsm_x4(a[mt][0], a[mt][1], a[mt][2], a[mt][3], addr);
        }
#pragma unroll
        for (int p = 0; p < 3; p++) {
            const uint32_t bbase = so + A_STAGE_B + p * B_PLANE_B;
#pragma unroll
            for (int nt = 0; nt < 4; nt++) {
                uint32_t b0, b1;
                uint32_t addr = bbase + (warp_n * 32 + nt * 8 + (lane & 7)) * 48 + ((lane >> 3) & 1) * 16;
                ldsm_x2(b0, b1, addr);
                imma16832(d[p][0][nt], a[0], b0, b1);
                imma16832(d[p][1][nt], a[1], b0, b1);
            }
        }
    }
#undef LOAD_STAGE

    // epilogue: u = S1*d1 + S2*d2 + S3*d3 (fp32), write U1
    const int g  = lane >> 2;
    const int tg = lane & 3;
#pragma unroll
    for (int mt = 0; mt < 2; mt++) {
        int m0 = bm0 + warp_m * 32 + mt * 16 + g;
#pragma unroll
        for (int nt = 0; nt < 4; nt++) {
            int n0 = bn0 + warp_n * 32 + nt * 8 + tg * 2;
            float v[4];
#pragma unroll
            for (int q = 0; q < 4; q++) {
                v[q] = fmaf((float)d[0][mt][nt][q], S1,
                        fmaf((float)d[1][mt][nt][q], S2,
                             (float)d[2][mt][nt][q] * S3));
            }
            *(float2*)&g_U1[(size_t)m0 * HID + n0]       = make_float2(v[0], v[1]);
            *(float2*)&g_U1[(size_t)(m0 + 8) * HID + n0] = make_float2(v[2], v[3]);
        }
    }
}

// ---------------- scan1: LIF hidden + fused sparse GEMM2 ------------------
__global__ void scan1_kernel(float4* __restrict__ out, const float* __restrict__ W2) {
    const int idx = blockIdx.x * blockDim.x + threadIdx.x;   // 0..65535
    const float4* u = reinterpret_cast<const float4*>(g_U1);
    const int j0 = idx * 4;
    const int b  = j0 >> 10;
    const int h0 = j0 & 1023;
    float4 mem = make_float4(0.f, 0.f, 0.f, 0.f);
#pragma unroll 4
    for (int t = 0; t < T_STEPS; t++) {
        float4 v = __ldcg(&u[(size_t)t * (BH / 4) + idx]);
        float4 s;
        mem.x = mem.x * DECAY + v.x; s.x = (mem.x >= THRESH) ? 1.f : 0.f; mem.x -= s.x * THRESH;
        mem.y = mem.y * DECAY + v.y; s.y = (mem.y >= THRESH) ? 1.f : 0.f; mem.y -= s.y * THRESH;
        mem.z = mem.z * DECAY + v.z; s.z = (mem.z >= THRESH) ? 1.f : 0.f; mem.z -= s.z * THRESH;
        mem.w = mem.w * DECAY + v.w; s.w = (mem.w >= THRESH) ? 1.f : 0.f; mem.w -= s.w * THRESH;
        out[(size_t)t * (BH / 4) + idx] = s;
        if (s.x + s.y + s.z + s.w > 0.f) {     // rare
            float sv[4] = {s.x, s.y, s.z, s.w};
            float* u2 = g_U2 + (size_t)(t * BATCH + b) * OUT_DIM;
#pragma unroll
            for (int q = 0; q < 4; q++) {
                if (sv[q] != 0.f) {
                    const float* w = W2 + (h0 + q) * OUT_DIM;
#pragma unroll
                    for (int o = 0; o < OUT_DIM; o++) atomicAdd(&u2[o], w[o]);
                }
            }
        }
    }
}

// ------------------------- scan2: smem-staged LIF output ------------------
__global__ void scan2_kernel(float* __restrict__ out2) {
    extern __shared__ float sm[];                 // [100][128]
    const int tid = threadIdx.x;
    const int lane0 = blockIdx.x * 128;
#pragma unroll 10
    for (int t = 0; t < T_STEPS; t++)
        sm[t * 128 + tid] = g_U2[(size_t)t * BO + lane0 + tid];
    float mem = 0.0f;
#pragma unroll 5
    for (int t = 0; t < T_STEPS; t++) {
        float u = sm[t * 128 + tid];
        mem = mem * DECAY + u;
        float s = (mem >= THRESH) ? 1.0f : 0.0f;
        mem -= s * THRESH;
        out2[(size_t)t * BO + lane0 + tid] = s;
    }
}

// ------------------------- launch ------------------------------------------
extern "C" void kernel_launch(void* const* d_in, const int* in_sizes, int n_in,
                              void* d_out, int out_size) {
    const float* X  = (const float*)d_in[0];
    const float* W1 = (const float*)d_in[1];
    const float* W2 = (const float*)d_in[2];
    float* out = (float*)d_out;
    (void)in_sizes; (void)n_in; (void)out_size;

    static bool attr_done = false;
    if (!attr_done) {
        cudaFuncSetAttribute(gemm1_kernel, cudaFuncAttributeMaxDynamicSharedMemorySize, SMEM_TOTAL);
        cudaFuncSetAttribute(scan2_kernel, cudaFuncAttributeMaxDynamicSharedMemorySize, 51200);
        attr_done = true;
    }

    prep_kernel<<<PREPX_BLKS + PREPW_BLKS + ZERO_BLKS, 256>>>(X, W1);

    gemm1_kernel<<<dim3(16, 200), 256, SMEM_TOTAL>>>();

    scan1_kernel<<<128, 512>>>((float4*)out, W2);

    scan2_kernel<<<20, 128, 51200>>>(out + HID_OUT);
}

// round 9
// speedup vs baseline: 3.2848x; 3.2848x over previous
#include <cuda_runtime.h>
#include <cuda_bf16.h>
#include <cstdint>
#include <cstddef>

// Problem dims (fixed)
#define T_STEPS 100
#define BATCH   256
#define IN_DIM  784
#define HID     1024
#define OUT_DIM 10
#define MROWS   25600
#define BH      262144
#define BO      2560
#define HID_OUT ((size_t)MROWS * HID)
#define THRESH 0.9f
#define DECAY  0.6f

// GEMM1 tiling: 128x128 CTA tile, BK=16, 49 k-iters, 6-stage cp.async ring
#define NKIT 49
#define NSTAGE 6
#define A_STAGE_B 6144u     // 128 rows * 24 bf16 (48B, padded)
#define B_PLANE_B 4352u     // 16 rows * 136 bf16 (272B, padded)
#define STAGE_B  14848u     // A + 2 B planes
#define SMEM_TOTAL (NSTAGE * STAGE_B)   // 89088 -> 2 CTAs/SM (178KB)

// ------------------------- scratch (device globals) -----------------------
__device__ __nv_bfloat16 g_Xbf[(size_t)MROWS * IN_DIM];        // 40.1 MB
__device__ __nv_bfloat16 g_W1c[(size_t)2 * IN_DIM * HID];      // hi rows 0..783, lo rows 784..1567
__device__ float         g_U1[(size_t)MROWS * HID];            // 104.9 MB
__device__ float         g_U2[(size_t)MROWS * OUT_DIM];        // 1.0 MB

// ------------------------- helpers ---------------------------------------
__device__ __forceinline__ uint32_t smem_u32(const void* p) {
    uint32_t a;
    asm("{ .reg .u64 t; cvta.to.shared.u64 t, %1; cvt.u32.u64 %0, t; }" : "=r"(a) : "l"(p));
    return a;
}
__device__ __forceinline__ void cpa16(uint32_t s, const void* g) {
    asm volatile("cp.async.cg.shared.global [%0], [%1], 16;\n" :: "r"(s), "l"(g));
}
__device__ __forceinline__ void ldsm_x4(uint32_t& r0, uint32_t& r1, uint32_t& r2, uint32_t& r3, uint32_t addr) {
    asm volatile("ldmatrix.sync.aligned.m8n8.x4.shared.b16 {%0,%1,%2,%3}, [%4];\n"
                 : "=r"(r0), "=r"(r1), "=r"(r2), "=r"(r3) : "r"(addr));
}
__device__ __forceinline__ void ldsm_x4_t(uint32_t& r0, uint32_t& r1, uint32_t& r2, uint32_t& r3, uint32_t addr) {
    asm volatile("ldmatrix.sync.aligned.m8n8.x4.trans.shared.b16 {%0,%1,%2,%3}, [%4];\n"
                 : "=r"(r0), "=r"(r1), "=r"(r2), "=r"(r3) : "r"(addr));
}
__device__ __forceinline__ void mma16816(float* c, const uint32_t* a, uint32_t b0, uint32_t b1) {
    asm volatile(
        "mma.sync.aligned.m16n8k16.row.col.f32.bf16.bf16.f32 "
        "{%0,%1,%2,%3}, {%4,%5,%6,%7}, {%8,%9}, {%0,%1,%2,%3};\n"
        : "+f"(c[0]), "+f"(c[1]), "+f"(c[2]), "+f"(c[3])
        : "r"(a[0]), "r"(a[1]), "r"(a[2]), "r"(a[3]), "r"(b0), "r"(b1));
}

// ------------------------- fused prep kernel -------------------------------
// Blocks [0, 19600): X fp32 -> bf16 (exact; one float4->bf16x4 per thread)
// Blocks [19600, 22736): W1 split hi/lo bf16 planes
// Blocks [22736, 22986): zero U2
#define PREPX_BLKS 19600
#define PREPW_BLKS 3136
#define ZERO_BLKS  250
__global__ void prep_kernel(const float4* __restrict__ x, const float* __restrict__ w1) {
    const int bid = blockIdx.x;
    if (bid < PREPX_BLKS) {
        int i = bid * 256 + threadIdx.x;                  // < 5,017,600
        float4 v = x[i];
        __nv_bfloat162* dst = reinterpret_cast<__nv_bfloat162*>(g_Xbf);
        dst[2 * i]     = __floats2bfloat162_rn(v.x, v.y);
        dst[2 * i + 1] = __floats2bfloat162_rn(v.z, v.w);
    } else if (bid < PREPX_BLKS + PREPW_BLKS) {
        int i = (bid - PREPX_BLKS) * 256 + threadIdx.x;   // < 802816
        float w = w1[i];
        __nv_bfloat16 hi = __float2bfloat16(w);
        __nv_bfloat16 lo = __float2bfloat16(w - __bfloat162float(hi));
        g_W1c[i] = hi;
        g_W1c[802816 + i] = lo;
    } else {
        int i = (bid - PREPX_BLKS - PREPW_BLKS) * 256 + threadIdx.x;  // < 64000
        reinterpret_cast<float4*>(g_U2)[i] = make_float4(0.f, 0.f, 0.f, 0.f);
    }
}

// ------------------------- GEMM1: U1 = X @ (W1hi + W1lo) ------------------
// 8 warps (2x4), warp tile 64x32, fp32 accum; hi/lo passes share the A tile.
__global__ __launch_bounds__(256, 2) void gemm1_kernel() {
    extern __shared__ char smem[];
    const uint32_t sbase = smem_u32(smem);

    const int tid = threadIdx.x;
    const int bn0 = blockIdx.x * 128;
    const int bm0 = blockIdx.y * 128;

    const int lane   = tid & 31;
    const int wid    = tid >> 5;
    const int warp_m = wid >> 2;   // 0..1
    const int warp_n = wid & 3;    // 0..3

    float acc[4][4][4];
#pragma unroll
    for (int i = 0; i < 4; i++)
#pragma unroll
        for (int j = 0; j < 4; j++)
#pragma unroll
            for (int k = 0; k < 4; k++) acc[i][j][k] = 0.0f;

    // producer addressing
    const int arow = tid >> 1, ach = tid & 1;
    const __nv_bfloat16* agp = g_Xbf + (size_t)(bm0 + arow) * IN_DIM + ach * 8;
    const int brow = tid >> 4, bch = tid & 15;
    const __nv_bfloat16* bgp = g_W1c + (size_t)brow * HID + bn0 + bch * 8;

    const uint32_t a_dst = sbase + arow * 48 + ach * 16;
    const uint32_t b_dst = sbase + A_STAGE_B + brow * 272 + bch * 16;

#define LOAD_STAGE(slot, kt) do {                                                   \
        uint32_t so = (slot) * STAGE_B;                                             \
        const __nv_bfloat16* a = agp + (size_t)(kt) * 16;                           \
        const __nv_bfloat16* b = bgp + (size_t)(kt) * 16 * HID;                     \
        cpa16(a_dst + so, a);                                                       \
        cpa16(b_dst + so, b);                                                       \
        cpa16(b_dst + so + B_PLANE_B, b + 802816);                                  \
        asm volatile("cp.async.commit_group;\n" ::: "memory");                      \
    } while (0)

    LOAD_STAGE(0, 0);
    LOAD_STAGE(1, 1);
    LOAD_STAGE(2, 2);
    LOAD_STAGE(3, 3);
    LOAD_STAGE(4, 4);

    for (int kt = 0; kt < NKIT; kt++) {
        const int cur = kt % NSTAGE;
        asm volatile("cp.async.wait_group 4;\n" ::: "memory");
        __syncthreads();

        // prefetch 5 ahead into the slot consumed last iteration
        if (kt + 5 < NKIT) {
            LOAD_STAGE((kt + 5) % NSTAGE, kt + 5);
        } else {
            asm volatile("cp.async.commit_group;\n" ::: "memory");
        }

        const uint32_t so = sbase + cur * STAGE_B;

        // A fragments (shared by hi/lo passes)
        uint32_t a[4][4];
#pragma unroll
        for (int mt = 0; mt < 4; mt++) {
            int row = warp_m * 64 + mt * 16 + (lane & 15);
            uint32_t addr = so + row * 48 + (lane >> 4) * 16;
            ldsm_x4(a[mt][0], a[mt][1], a[mt][2], a[mt][3], addr);
        }
#pragma unroll
        for (int p = 0; p < 2; p++) {
#pragma unroll
            for (int nt = 0; nt < 2; nt++) {
                uint32_t b0, b1, b2, b3;
                int krow = lane & 15;
                int col  = warp_n * 32 + nt * 16 + (lane >> 4) * 8;
                uint32_t addr = so + A_STAGE_B + p * B_PLANE_B + krow * 272 + col * 2;
                ldsm_x4_t(b0, b1, b2, b3, addr);
#pragma unroll
                for (int mt = 0; mt < 4; mt++) {
                    mma16816(acc[mt][nt * 2],     a[mt], b0, b1);
                    mma16816(acc[mt][nt * 2 + 1], a[mt], b2, b3);
                }
            }
        }
    }
#undef LOAD_STAGE

    // epilogue: write U1 (fp32)
    const int g  = lane >> 2;
    const int tg = lane & 3;
#pragma unroll
    for (int mt = 0; mt < 4; mt++) {
        int m0 = bm0 + warp_m * 64 + mt * 16 + g;
#pragma unroll
        for (int nf = 0; nf < 4; nf++) {
            int n0 = bn0 + warp_n * 32 + nf * 8 + tg * 2;
            float2 v0 = make_float2(acc[mt][nf][0], acc[mt][nf][1]);
            float2 v1 = make_float2(acc[mt][nf][2], acc[mt][nf][3]);
            *(float2*)&g_U1[(size_t)m0 * HID + n0]       = v0;
            *(float2*)&g_U1[(size_t)(m0 + 8) * HID + n0] = v1;
        }
    }
}

// ---------------- scan1: LIF hidden + fused sparse GEMM2 ------------------
// One thread per 4 (b,h) lanes. On the (rare) spike, scatter W2 row into U2.
__global__ void scan1_kernel(float4* __restrict__ out, const float* __restrict__ W2) {
    const int idx = blockIdx.x * blockDim.x + threadIdx.x;   // 0..65535
    const float4* u = reinterpret_cast<const float4*>(g_U1);
    const int j0 = idx * 4;
    const int b  = j0 >> 10;
    const int h0 = j0 & 1023;
    float4 mem = make_float4(0.f, 0.f, 0.f, 0.f);
#pragma unroll 4
    for (int t = 0; t < T_STEPS; t++) {
        float4 v = __ldcg(&u[(size_t)t * (BH / 4) + idx]);
        float4 s;
        mem.x = mem.x * DECAY + v.x; s.x = (mem.x >= THRESH) ? 1.f : 0.f; mem.x -= s.x * THRESH;
        mem.y = mem.y * DECAY + v.y; s.y = (mem.y >= THRESH) ? 1.f : 0.f; mem.y -= s.y * THRESH;
        mem.z = mem.z * DECAY + v.z; s.z = (mem.z >= THRESH) ? 1.f : 0.f; mem.z -= s.z * THRESH;
        mem.w = mem.w * DECAY + v.w; s.w = (mem.w >= THRESH) ? 1.f : 0.f; mem.w -= s.w * THRESH;
        out[(size_t)t * (BH / 4) + idx] = s;
        if (s.x + s.y + s.z + s.w > 0.f) {     // rare (~1900 spikes total)
            float sv[4] = {s.x, s.y, s.z, s.w};
            float* u2 = g_U2 + (size_t)(t * BATCH + b) * OUT_DIM;
#pragma unroll
            for (int q = 0; q < 4; q++) {
                if (sv[q] != 0.f) {
                    const float* w = W2 + (h0 + q) * OUT_DIM;
#pragma unroll
                    for (int o = 0; o < OUT_DIM; o++) atomicAdd(&u2[o], w[o]);
                }
            }
        }
    }
}

// ------------------------- scan2: smem-staged LIF output ------------------
// 20 blocks x 128 threads; block stages its [100][128] U2 slice into smem
// with fully parallel coalesced loads, then scans (threads read only their
// own smem writes -> no barrier needed).
__global__ void scan2_kernel(float* __restrict__ out2) {
    extern __shared__ float sm[];                 // [100][128]
    const int tid = threadIdx.x;
    const int lane0 = blockIdx.x * 128;
#pragma unroll 10
    for (int t = 0; t < T_STEPS; t++)
        sm[t * 128 + tid] = g_U2[(size_t)t * BO + lane0 + tid];
    float mem = 0.0f;
#pragma unroll 5
    for (int t = 0; t < T_STEPS; t++) {
        float u = sm[t * 128 + tid];
        mem = mem * DECAY + u;
        float s = (mem >= THRESH) ? 1.0f : 0.0f;
        mem -= s * THRESH;
        out2[(size_t)t * BO + lane0 + tid] = s;
    }
}

// ------------------------- launch ------------------------------------------
extern "C" void kernel_launch(void* const* d_in, const int* in_sizes, int n_in,
                              void* d_out, int out_size) {
    const float* X  = (const float*)d_in[0];
    const float* W1 = (const float*)d_in[1];
    const float* W2 = (const float*)d_in[2];
    float* out = (float*)d_out;
    (void)in_sizes; (void)n_in; (void)out_size;

    static bool attr_done = false;
    if (!attr_done) {
        cudaFuncSetAttribute(gemm1_kernel, cudaFuncAttributeMaxDynamicSharedMemorySize, SMEM_TOTAL);
        cudaFuncSetAttribute(scan2_kernel, cudaFuncAttributeMaxDynamicSharedMemorySize, 51200);
        attr_done = true;
    }

    prep_kernel<<<PREPX_BLKS + PREPW_BLKS + ZERO_BLKS, 256>>>((const float4*)X, W1);

    gemm1_kernel<<<dim3(8, 200), 256, SMEM_TOTAL>>>();

    scan1_kernel<<<128, 512>>>((float4*)out, W2);

    scan2_kernel<<<20, 128, 51200>>>(out + HID_OUT);
}

// round 11
// speedup vs baseline: 3.4473x; 1.0495x over previous
#include <cuda_runtime.h>
#include <cuda_bf16.h>
#include <cstdint>
#include <cstddef>

// Problem dims (fixed)
#define T_STEPS 100
#define BATCH   256
#define IN_DIM  784
#define HID     1024
#define OUT_DIM 10
#define MROWS   25600
#define BH      262144
#define BO      2560
#define HID_OUT ((size_t)MROWS * HID)
#define THRESH 0.9f
#define DECAY  0.6f

// GEMM1 tiling: 128x128 CTA tile, BK=16, 49 k-iters, 6-stage cp.async ring
#define NKIT 49
#define NSTAGE 6
#define A_STAGE_B 6144u     // 128 rows * 24 bf16 (48B, padded)
#define B_PLANE_B 4352u     // 16 rows * 136 bf16 (272B, padded)
#define STAGE_B  14848u     // A + 2 B planes
#define SMEM_TOTAL (NSTAGE * STAGE_B)   // 89088 -> 2 CTAs/SM (178KB)

// ------------------------- scratch (device globals) -----------------------
__device__ __nv_bfloat16 g_Xbf[(size_t)MROWS * IN_DIM];        // 40.1 MB
__device__ __nv_bfloat16 g_W1c[(size_t)2 * IN_DIM * HID];      // hi rows 0..783, lo rows 784..1567
__device__ float         g_U1[(size_t)MROWS * HID];            // 104.9 MB
__device__ float         g_U2[(size_t)MROWS * OUT_DIM];        // 1.0 MB

// ------------------------- helpers ---------------------------------------
__device__ __forceinline__ uint32_t smem_u32(const void* p) {
    uint32_t a;
    asm("{ .reg .u64 t; cvta.to.shared.u64 t, %1; cvt.u32.u64 %0, t; }" : "=r"(a) : "l"(p));
    return a;
}
__device__ __forceinline__ void cpa16(uint32_t s, const void* g) {
    asm volatile("cp.async.cg.shared.global [%0], [%1], 16;\n" :: "r"(s), "l"(g));
}
__device__ __forceinline__ void ldsm_x4(uint32_t& r0, uint32_t& r1, uint32_t& r2, uint32_t& r3, uint32_t addr) {
    asm volatile("ldmatrix.sync.aligned.m8n8.x4.shared.b16 {%0,%1,%2,%3}, [%4];\n"
                 : "=r"(r0), "=r"(r1), "=r"(r2), "=r"(r3) : "r"(addr));
}
__device__ __forceinline__ void ldsm_x4_t(uint32_t& r0, uint32_t& r1, uint32_t& r2, uint32_t& r3, uint32_t addr) {
    asm volatile("ldmatrix.sync.aligned.m8n8.x4.trans.shared.b16 {%0,%1,%2,%3}, [%4];\n"
                 : "=r"(r0), "=r"(r1), "=r"(r2), "=r"(r3) : "r"(addr));
}
__device__ __forceinline__ void mma16816(float* c, const uint32_t* a, uint32_t b0, uint32_t b1) {
    asm volatile(
        "mma.sync.aligned.m16n8k16.row.col.f32.bf16.bf16.f32 "
        "{%0,%1,%2,%3}, {%4,%5,%6,%7}, {%8,%9}, {%0,%1,%2,%3};\n"
        : "+f"(c[0]), "+f"(c[1]), "+f"(c[2]), "+f"(c[3])
        : "r"(a[0]), "r"(a[1]), "r"(a[2]), "r"(a[3]), "r"(b0), "r"(b1));
}

// ------------------------- fused prep kernel -------------------------------
#define PREPX_BLKS 19600
#define PREPW_BLKS 3136
#define ZERO_BLKS  250
__global__ void prep_kernel(const float4* __restrict__ x, const float* __restrict__ w1) {
    const int bid = blockIdx.x;
    if (bid < PREPX_BLKS) {
        int i = bid * 256 + threadIdx.x;                  // < 5,017,600
        float4 v = x[i];
        __nv_bfloat162* dst = reinterpret_cast<__nv_bfloat162*>(g_Xbf);
        dst[2 * i]     = __floats2bfloat162_rn(v.x, v.y);
        dst[2 * i + 1] = __floats2bfloat162_rn(v.z, v.w);
    } else if (bid < PREPX_BLKS + PREPW_BLKS) {
        int i = (bid - PREPX_BLKS) * 256 + threadIdx.x;   // < 802816
        float w = w1[i];
        __nv_bfloat16 hi = __float2bfloat16(w);
        __nv_bfloat16 lo = __float2bfloat16(w - __bfloat162float(hi));
        g_W1c[i] = hi;
        g_W1c[802816 + i] = lo;
    } else {
        int i = (bid - PREPX_BLKS - PREPW_BLKS) * 256 + threadIdx.x;  // < 64000
        reinterpret_cast<float4*>(g_U2)[i] = make_float4(0.f, 0.f, 0.f, 0.f);
    }
}

// ------------------------- GEMM1: U1 = X @ (W1hi + W1lo) ------------------
// 8 warps (2x4), warp tile 64x32, fp32 accum; hi/lo passes share the A tile.
__global__ __launch_bounds__(256, 2) void gemm1_kernel() {
    extern __shared__ char smem[];
    const uint32_t sbase = smem_u32(smem);

    const int tid = threadIdx.x;
    const int bn0 = blockIdx.x * 128;
    const int bm0 = blockIdx.y * 128;

    const int lane   = tid & 31;
    const int wid    = tid >> 5;
    const int warp_m = wid >> 2;   // 0..1
    const int warp_n = wid & 3;    // 0..3

    float acc[4][4][4];
#pragma unroll
    for (int i = 0; i < 4; i++)
#pragma unroll
        for (int j = 0; j < 4; j++)
#pragma unroll
            for (int k = 0; k < 4; k++) acc[i][j][k] = 0.0f;

    // producer addressing
    const int arow = tid >> 1, ach = tid & 1;
    const __nv_bfloat16* agp = g_Xbf + (size_t)(bm0 + arow) * IN_DIM + ach * 8;
    const int brow = tid >> 4, bch = tid & 15;
    const __nv_bfloat16* bgp = g_W1c + (size_t)brow * HID + bn0 + bch * 8;

    const uint32_t a_dst = sbase + arow * 48 + ach * 16;
    const uint32_t b_dst = sbase + A_STAGE_B + brow * 272 + bch * 16;

#define LOAD_STAGE(slot, kt) do {                                                   \
        uint32_t so = (slot) * STAGE_B;                                             \
        const __nv_bfloat16* a = agp + (size_t)(kt) * 16;                           \
        const __nv_bfloat16* b = bgp + (size_t)(kt) * 16 * HID;                     \
        cpa16(a_dst + so, a);                                                       \
        cpa16(b_dst + so, b);                                                       \
        cpa16(b_dst + so + B_PLANE_B, b + 802816);                                  \
        asm volatile("cp.async.commit_group;\n" ::: "memory");                      \
    } while (0)

    LOAD_STAGE(0, 0);
    LOAD_STAGE(1, 1);
    LOAD_STAGE(2, 2);
    LOAD_STAGE(3, 3);
    LOAD_STAGE(4, 4);

    for (int kt = 0; kt < NKIT; kt++) {
        const int cur = kt % NSTAGE;
        asm volatile("cp.async.wait_group 4;\n" ::: "memory");
        __syncthreads();

        // prefetch 5 ahead into the slot consumed last iteration
        if (kt + 5 < NKIT) {
            LOAD_STAGE((kt + 5) % NSTAGE, kt + 5);
        } else {
            asm volatile("cp.async.commit_group;\n" ::: "memory");
        }

        const uint32_t so = sbase + cur * STAGE_B;

        // A fragments (shared by hi/lo passes)
        uint32_t a[4][4];
#pragma unroll
        for (int mt = 0; mt < 4; mt++) {
            int row = warp_m * 64 + mt * 16 + (lane & 15);
            uint32_t addr = so + row * 48 + (lane >> 4) * 16;
            ldsm_x4(a[mt][0], a[mt][1], a[mt][2], a[mt][3], addr);
        }
#pragma unroll
        for (int p = 0; p < 2; p++) {
            // hoist both B ldsm of this pass before the 16 MMAs
            uint32_t b[2][4];
#pragma unroll
            for (int nt = 0; nt < 2; nt++) {
                int krow = lane & 15;
                int col  = warp_n * 32 + nt * 16 + (lane >> 4) * 8;
                uint32_t addr = so + A_STAGE_B + p * B_PLANE_B + krow * 272 + col * 2;
                ldsm_x4_t(b[nt][0], b[nt][1], b[nt][2], b[nt][3], addr);
            }
#pragma unroll
            for (int nt = 0; nt < 2; nt++) {
#pragma unroll
                for (int mt = 0; mt < 4; mt++) {
                    mma16816(acc[mt][nt * 2],     a[mt], b[nt][0], b[nt][1]);
                    mma16816(acc[mt][nt * 2 + 1], a[mt], b[nt][2], b[nt][3]);
                }
            }
        }
    }
#undef LOAD_STAGE

    // epilogue: write U1 (fp32)
    const int g  = lane >> 2;
    const int tg = lane & 3;
#pragma unroll
    for (int mt = 0; mt < 4; mt++) {
        int m0 = bm0 + warp_m * 64 + mt * 16 + g;
#pragma unroll
        for (int nf = 0; nf < 4; nf++) {
            int n0 = bn0 + warp_n * 32 + nf * 8 + tg * 2;
            float2 v0 = make_float2(acc[mt][nf][0], acc[mt][nf][1]);
            float2 v1 = make_float2(acc[mt][nf][2], acc[mt][nf][3]);
            *(float2*)&g_U1[(size_t)m0 * HID + n0]       = v0;
            *(float2*)&g_U1[(size_t)(m0 + 8) * HID + n0] = v1;
        }
    }
}

// ---------------- scan1: LIF hidden + fused sparse GEMM2 ------------------
// One thread per 4 (b,h) lanes; software-pipelined load (1-deep prefetch).
// On the (rare) spike, scatter W2 row into U2.
__global__ void scan1_kernel(float4* __restrict__ out, const float* __restrict__ W2) {
    const int idx = blockIdx.x * blockDim.x + threadIdx.x;   // 0..65535
    const float4* u = reinterpret_cast<const float4*>(g_U1);
    const int j0 = idx * 4;
    const int b  = j0 >> 10;
    const int h0 = j0 & 1023;
    float4 mem = make_float4(0.f, 0.f, 0.f, 0.f);
    float4 vnext = __ldcg(&u[idx]);
#pragma unroll 4
    for (int t = 0; t < T_STEPS; t++) {
        float4 v = vnext;
        if (t + 1 < T_STEPS) vnext = __ldcg(&u[(size_t)(t + 1) * (BH / 4) + idx]);
        float4 s;
        mem.x = mem.x * DECAY + v.x; s.x = (mem.x >= THRESH) ? 1.f : 0.f; mem.x -= s.x * THRESH;
        mem.y = mem.y * DECAY + v.y; s.y = (mem.y >= THRESH) ? 1.f : 0.f; mem.y -= s.y * THRESH;
        mem.z = mem.z * DECAY + v.z; s.z = (mem.z >= THRESH) ? 1.f : 0.f; mem.z -= s.z * THRESH;
        mem.w = mem.w * DECAY + v.w; s.w = (mem.w >= THRESH) ? 1.f : 0.f; mem.w -= s.w * THRESH;
        out[(size_t)t * (BH / 4) + idx] = s;
        if (s.x + s.y + s.z + s.w > 0.f) {     // rare (~1900 spikes total)
            float sv[4] = {s.x, s.y, s.z, s.w};
            float* u2 = g_U2 + (size_t)(t * BATCH + b) * OUT_DIM;
#pragma unroll
            for (int q = 0; q < 4; q++) {
                if (sv[q] != 0.f) {
                    const float* w = W2 + (h0 + q) * OUT_DIM;
#pragma unroll
                    for (int o = 0; o < OUT_DIM; o++) atomicAdd(&u2[o], w[o]);
                }
            }
        }
    }
}

// ------------------------- scan2: cooperatively staged LIF output ---------
// 20 blocks x 512 threads; ALL 512 threads stage the [100][128] U2 slice
// (25 fully parallel coalesced loads each), then 128 threads scan from smem.
__global__ void scan2_kernel(float* __restrict__ out2) {
    extern __shared__ float sm[];                 // [100][128]
    const int tid = threadIdx.x;
    const int lane0 = blockIdx.x * 128;
#pragma unroll
    for (int i = tid; i < T_STEPS * 128; i += 512) {
        int t = i >> 7, lane = i & 127;
        sm[i] = g_U2[(size_t)t * BO + lane0 + lane];
    }
    __syncthreads();
    if (tid < 128) {
        float mem = 0.0f;
#pragma unroll 5
        for (int t = 0; t < T_STEPS; t++) {
            float u = sm[t * 128 + tid];
            mem = mem * DECAY + u;
            float s = (mem >= THRESH) ? 1.0f : 0.0f;
            mem -= s * THRESH;
            out2[(size_t)t * BO + lane0 + tid] = s;
        }
    }
}

// ------------------------- launch ------------------------------------------
extern "C" void kernel_launch(void* const* d_in, const int* in_sizes, int n_in,
                              void* d_out, int out_size) {
    const float* X  = (const float*)d_in[0];
    const float* W1 = (const float*)d_in[1];
    const float* W2 = (const float*)d_in[2];
    float* out = (float*)d_out;
    (void)in_sizes; (void)n_in; (void)out_size;

    static bool attr_done = false;
    if (!attr_done) {
        cudaFuncSetAttribute(gemm1_kernel, cudaFuncAttributeMaxDynamicSharedMemorySize, SMEM_TOTAL);
        cudaFuncSetAttribute(scan2_kernel, cudaFuncAttributeMaxDynamicSharedMemorySize, 51200);
        attr_done = true;
    }

    prep_kernel<<<PREPX_BLKS + PREPW_BLKS + ZERO_BLKS, 256>>>((const float4*)X, W1);

    gemm1_kernel<<<dim3(8, 200), 256, SMEM_TOTAL>>>();

    scan1_kernel<<<128, 512>>>((float4*)out, W2);

    scan2_kernel<<<20, 512, 51200>>>(out + HID_OUT);
}